// round 14
// baseline (speedup 1.0000x reference)
#include <cuda_runtime.h>
#include <math.h>

#define BB 4
#define NN 2048
#define CC 32
#define CONV 332.07156f
#define EPS 1e-6f

// ---- precompute geometry ----
#define PRE_THREADS 256
#define PRE_BLOCKS (BB * NN / PRE_THREADS)   // 32 (8 per batch)

// ---- pair geometry (symmetric 256-row panels, fine-grained) ----
#define PTHREADS 128
#define PIB 2                       // i-atoms per thread -> panel = 256
#define PANEL 256
#define BLKS_PER_B 370              // splits 82+72+62+51+41+31+21+10 (8 panels)
#define PBLOCKS (BB * BLKS_PER_B)   // 1480 blocks

// Scratch (no cudaMalloc allowed)
__device__ float4 g_S[BB * NN];            // {-x, -y, -z, w=s_i+s_j}
__device__ double g_part_pair[PBLOCKS];
__device__ double g_part_self[PRE_BLOCKS]; // self + 0.5*diag-correction
__device__ unsigned int g_counter = 0;

// ============ kernel 1: per-atom precompute + self/diag partials ============
__global__ void __launch_bounds__(PRE_THREADS)
precompute_kernel(const float* __restrict__ X,
                  const float* __restrict__ embs,
                  const float* __restrict__ qs,
                  const float* __restrict__ born,
                  const float* __restrict__ die,
                  const float* __restrict__ filt)
{
    __shared__ double red[PRE_THREADS / 32];
    const int tid = threadIdx.x;
    const int idx = blockIdx.x * PRE_THREADS + tid;
    const float wd = filt[2 * CC];

    const float4* e4 = (const float4*)(embs + (long)idx * CC);
    const float4* fi = (const float4*)(filt);
    const float4* fj = (const float4*)(filt + CC);
    const float4* d4 = (const float4*)(die);
    const float4* b4 = (const float4*)(born);

    float si = 0.f, sj = 0.f, ad = EPS, R = 1.0f;
#pragma unroll
    for (int c = 0; c < CC / 4; c++) {
        float4 e = e4[c];
        float4 a = fi[c], bq = fj[c], d = d4[c], bo = b4[c];
        si = fmaf(e.x, a.x,  fmaf(e.y, a.y,  fmaf(e.z, a.z,  fmaf(e.w, a.w,  si))));
        sj = fmaf(e.x, bq.x, fmaf(e.y, bq.y, fmaf(e.z, bq.z, fmaf(e.w, bq.w, sj))));
        ad = fmaf(e.x, d.x,  fmaf(e.y, d.y,  fmaf(e.z, d.z,  fmaf(e.w, d.w,  ad))));
        R  = fmaf(e.x, bo.x, fmaf(e.y, bo.y, fmaf(e.z, bo.z, fmaf(e.w, bo.w, R))));
    }
    float es = -(1.0f - 1.0f / ad) * qs[idx] / (R + EPS);

    g_S[idx] = make_float4(-X[idx * 3 + 0], -X[idx * 3 + 1], -X[idx * 3 + 2],
                           si + sj);

    // exact diagonal correction: the pair loop credits (si+sj)*r0_hw + wd
    // for the j==i pair; the true value is (si+sj+wd*D0)/(D0+eps).
    double part;
    {
        float d2c = 3e-6f;
        asm volatile("" : "+f"(d2c));        // block constant folding
        float r0_hw = rsqrtf(d2c);           // identical MUFU value as pair loop
        double D0 = (double)sqrtf(d2c);
        double w  = (double)si + (double)sj;
        double exact = (w + (double)wd * D0) / (D0 + (double)EPS);
        double loopv = w * (double)r0_hw + (double)wd;
        double corr = exact - loopv;          // pair-sum channel (coeff 0.5)
        part = (double)es + 0.5 * corr;
    }
#pragma unroll
    for (int off = 16; off > 0; off >>= 1)
        part += __shfl_down_sync(0xffffffffu, part, off);
    if ((tid & 31) == 0) red[tid >> 5] = part;
    __syncthreads();
    if (tid == 0) {
        double s = 0.0;
#pragma unroll
        for (int w = 0; w < PRE_THREADS / 32; w++) s += red[w];
        g_part_self[blockIdx.x] = s;
    }
}

// ============ kernel 2: symmetric pairwise + finalize ============
__global__ void __launch_bounds__(PTHREADS, 8)
pair_kernel(const float* __restrict__ filt, float* __restrict__ out)
{
    __shared__ float redf[PTHREADS / 32];
    __shared__ bool isLast;

    const int tid = threadIdx.x;
    const int blk = blockIdx.x;
    const int b   = blk / BLKS_PER_B;
    const int r   = blk % BLKS_PER_B;

    // panel + split within panel; splits: 82,72,62,51,41,31,21,10 (sum 370)
    int p, rl, ns;
    if      (r <  82) { p = 0; rl = r;       ns = 82; }
    else if (r < 154) { p = 1; rl = r -  82; ns = 72; }
    else if (r < 216) { p = 2; rl = r - 154; ns = 62; }
    else if (r < 267) { p = 3; rl = r - 216; ns = 51; }
    else if (r < 308) { p = 4; rl = r - 267; ns = 41; }
    else if (r < 339) { p = 5; rl = r - 308; ns = 31; }
    else if (r < 360) { p = 6; rl = r - 339; ns = 21; }
    else              { p = 7; rl = r - 360; ns = 10; }

    const int lo  = PANEL * p;
    const int len = NN - lo;
    const int j0  = lo + (rl * len) / ns;
    const int j1  = lo + ((rl + 1) * len) / ns;
    const int selfEnd = lo + PANEL;
    const int jA1 = (j1 < selfEnd) ? j1 : selfEnd;
    const int jB0 = (j0 > selfEnd) ? j0 : selfEnd;

    const float4* __restrict__ S = g_S + b * NN;

    float xi[PIB], yi[PIB], zi[PIB], wi[PIB], acc[PIB];
#pragma unroll
    for (int k = 0; k < PIB; k++) {
        float4 a = __ldg(&S[lo + k * PTHREADS + tid]);
        xi[k] = -a.x; yi[k] = -a.y; zi[k] = -a.z; wi[k] = a.w;
        acc[k] = 0.f;
    }
    float accw = 0.f;

    // ---- loop A: intra-panel (full matrix, w_i weight), MLP-4 chunks ----
    {
        int j = j0;
        for (; j + 4 <= jA1; j += 4) {
            float4 t0 = __ldg(&S[j + 0]);      // 4 independent LDG.128s
            float4 t1 = __ldg(&S[j + 1]);      // front-batched -> MLP=4
            float4 t2 = __ldg(&S[j + 2]);
            float4 t3 = __ldg(&S[j + 3]);
#pragma unroll
            for (int k = 0; k < PIB; k++) {
                float dx0 = xi[k] + t0.x, dy0 = yi[k] + t0.y, dz0 = zi[k] + t0.z;
                float dx1 = xi[k] + t1.x, dy1 = yi[k] + t1.y, dz1 = zi[k] + t1.z;
                float dx2 = xi[k] + t2.x, dy2 = yi[k] + t2.y, dz2 = zi[k] + t2.z;
                float dx3 = xi[k] + t3.x, dy3 = yi[k] + t3.y, dz3 = zi[k] + t3.z;
                float d0 = fmaf(dx0, dx0, fmaf(dy0, dy0, fmaf(dz0, dz0, 3e-6f)));
                float d1 = fmaf(dx1, dx1, fmaf(dy1, dy1, fmaf(dz1, dz1, 3e-6f)));
                float d2 = fmaf(dx2, dx2, fmaf(dy2, dy2, fmaf(dz2, dz2, 3e-6f)));
                float d3 = fmaf(dx3, dx3, fmaf(dy3, dy3, fmaf(dz3, dz3, 3e-6f)));
                acc[k] += rsqrtf(d0) + rsqrtf(d1) + rsqrtf(d2) + rsqrtf(d3);
            }
        }
        for (; j < jA1; j++) {
            float4 t0 = __ldg(&S[j]);
#pragma unroll
            for (int k = 0; k < PIB; k++) {
                float dx = xi[k] + t0.x, dy = yi[k] + t0.y, dz = zi[k] + t0.z;
                float d2 = fmaf(dx, dx, fmaf(dy, dy, fmaf(dz, dz, 3e-6f)));
                acc[k] += rsqrtf(d2);
            }
        }
    }

    // ---- loop B: cross-panel once, (w_i + w_j) weight, MLP-4 chunks ----
    {
        int j = jB0;
        for (; j + 4 <= j1; j += 4) {
            float4 t0 = __ldg(&S[j + 0]);
            float4 t1 = __ldg(&S[j + 1]);
            float4 t2 = __ldg(&S[j + 2]);
            float4 t3 = __ldg(&S[j + 3]);
            float r0s = 0.f, r1s = 0.f, r2s = 0.f, r3s = 0.f;
#pragma unroll
            for (int k = 0; k < PIB; k++) {
                float dx0 = xi[k] + t0.x, dy0 = yi[k] + t0.y, dz0 = zi[k] + t0.z;
                float dx1 = xi[k] + t1.x, dy1 = yi[k] + t1.y, dz1 = zi[k] + t1.z;
                float dx2 = xi[k] + t2.x, dy2 = yi[k] + t2.y, dz2 = zi[k] + t2.z;
                float dx3 = xi[k] + t3.x, dy3 = yi[k] + t3.y, dz3 = zi[k] + t3.z;
                float d0 = fmaf(dx0, dx0, fmaf(dy0, dy0, fmaf(dz0, dz0, 3e-6f)));
                float d1 = fmaf(dx1, dx1, fmaf(dy1, dy1, fmaf(dz1, dz1, 3e-6f)));
                float d2 = fmaf(dx2, dx2, fmaf(dy2, dy2, fmaf(dz2, dz2, 3e-6f)));
                float d3 = fmaf(dx3, dx3, fmaf(dy3, dy3, fmaf(dz3, dz3, 3e-6f)));
                float r0 = rsqrtf(d0), r1 = rsqrtf(d1), r2 = rsqrtf(d2), r3 = rsqrtf(d3);
                acc[k] += r0 + r1 + r2 + r3;
                r0s += r0; r1s += r1; r2s += r2; r3s += r3;
            }
            accw = fmaf(t0.w, r0s, accw);
            accw = fmaf(t1.w, r1s, accw);
            accw = fmaf(t2.w, r2s, accw);
            accw = fmaf(t3.w, r3s, accw);
        }
        for (; j < j1; j++) {
            float4 t0 = __ldg(&S[j]);
            float rs = 0.f;
#pragma unroll
            for (int k = 0; k < PIB; k++) {
                float dx = xi[k] + t0.x, dy = yi[k] + t0.y, dz = zi[k] + t0.z;
                float d2 = fmaf(dx, dx, fmaf(dy, dy, fmaf(dz, dz, 3e-6f)));
                float rr = rsqrtf(d2);
                acc[k] += rr; rs += rr;
            }
            accw = fmaf(t0.w, rs, accw);
        }
    }

    // ---- fp32 combine + warp reduce (FP64 only once per block) ----
    float part = accw;
#pragma unroll
    for (int k = 0; k < PIB; k++)
        part = fmaf(wi[k], acc[k], part);
#pragma unroll
    for (int off = 16; off > 0; off >>= 1)
        part += __shfl_down_sync(0xffffffffu, part, off);
    if ((tid & 31) == 0) redf[tid >> 5] = part;
    __syncthreads();
    if (tid == 0) {
        double s = 0.0;
#pragma unroll
        for (int w = 0; w < PTHREADS / 32; w++) s += (double)redf[w];
        g_part_pair[blk] = s;
        __threadfence();
        unsigned int t = atomicAdd(&g_counter, 1u);
        isLast = (t == (unsigned)(gridDim.x - 1));
    }
    __syncthreads();
    if (!isLast) return;

    // ---- finalize: warp w (w<BB) handles batch w ----
    const int w = tid >> 5, lane = tid & 31;
    const float wd = filt[2 * CC];

    if (w < BB) {
        double pp = 0.0;
#pragma unroll
        for (int t = 0; t < 12; t++) {
            int idx = lane + t * 32;
            if (idx < BLKS_PER_B) pp += __ldcg(&g_part_pair[w * BLKS_PER_B + idx]);
        }
        double ss = (lane < PRE_BLOCKS / BB)
                  ? __ldcg(&g_part_self[w * (PRE_BLOCKS / BB) + lane]) : 0.0;
#pragma unroll
        for (int off = 16; off > 0; off >>= 1) {
            pp += __shfl_down_sync(0xffffffffu, pp, off);
            ss += __shfl_down_sync(0xffffffffu, ss, off);
        }
        if (lane == 0) {
            double pair = pp + (double)wd * (double)NN * (double)NN;
            float v = (float)((double)CONV * (ss + 0.5 * pair) * 0.01);
            if (isnan(v)) v = 1e-6f;
            out[w] = v;
        }
    }
    if (tid == 0) g_counter = 0;   // reset for next graph replay
}

extern "C" void kernel_launch(void* const* d_in, const int* in_sizes, int n_in,
                              void* d_out, int out_size) {
    const float* X    = (const float*)d_in[0];  // (B,N,3)
    const float* embs = (const float*)d_in[1];  // (B,N,C)
    const float* qs   = (const float*)d_in[2];  // (B,N)
    // d_in[3] = paired_mask (unused by reference)
    const float* born = (const float*)d_in[4];  // (C,)
    const float* die  = (const float*)d_in[5];  // (C,)
    const float* filt = (const float*)d_in[6];  // (2C+1, 1)
    float* out = (float*)d_out;

    precompute_kernel<<<PRE_BLOCKS, PRE_THREADS>>>(X, embs, qs, born, die, filt);
    pair_kernel<<<PBLOCKS, PTHREADS>>>(filt, out);
}

// round 15
// speedup vs baseline: 1.0133x; 1.0133x over previous
#include <cuda_runtime.h>
#include <math.h>

#define BB 4
#define NN 2048
#define CC 32
#define CONV 332.07156f
#define EPS 1e-6f

// ---- precompute geometry ----
#define PRE_THREADS 256
#define PRE_BLOCKS (BB * NN / PRE_THREADS)   // 32 (8 per batch)

// ---- pair geometry (symmetric 256-row panels, fine-grained) ----
#define PTHREADS 128
#define PIB 2                       // i-atoms per thread -> panel = 256
#define PANEL 256
#define BLKS_PER_B 444              // splits 99+86+74+62+49+37+25+12 (8 panels)
#define PBLOCKS (BB * BLKS_PER_B)   // 1776 = 12 CTAs/SM x 4 warps = 48 warps/SM

// Scratch (no cudaMalloc allowed)
__device__ float4 g_S[BB * NN];            // {-x, -y, -z, w=s_i+s_j}
__device__ double g_part_pair[PBLOCKS];
__device__ double g_part_self[PRE_BLOCKS]; // self + 0.5*diag-correction
__device__ unsigned int g_counter = 0;

// ============ kernel 1: per-atom precompute + self/diag partials ============
__global__ void __launch_bounds__(PRE_THREADS)
precompute_kernel(const float* __restrict__ X,
                  const float* __restrict__ embs,
                  const float* __restrict__ qs,
                  const float* __restrict__ born,
                  const float* __restrict__ die,
                  const float* __restrict__ filt)
{
    __shared__ double red[PRE_THREADS / 32];
    const int tid = threadIdx.x;
    const int idx = blockIdx.x * PRE_THREADS + tid;
    const float wd = filt[2 * CC];

    const float4* e4 = (const float4*)(embs + (long)idx * CC);
    const float4* fi = (const float4*)(filt);
    const float4* fj = (const float4*)(filt + CC);
    const float4* d4 = (const float4*)(die);
    const float4* b4 = (const float4*)(born);

    float si = 0.f, sj = 0.f, ad = EPS, R = 1.0f;
#pragma unroll
    for (int c = 0; c < CC / 4; c++) {
        float4 e = e4[c];
        float4 a = fi[c], bq = fj[c], d = d4[c], bo = b4[c];
        si = fmaf(e.x, a.x,  fmaf(e.y, a.y,  fmaf(e.z, a.z,  fmaf(e.w, a.w,  si))));
        sj = fmaf(e.x, bq.x, fmaf(e.y, bq.y, fmaf(e.z, bq.z, fmaf(e.w, bq.w, sj))));
        ad = fmaf(e.x, d.x,  fmaf(e.y, d.y,  fmaf(e.z, d.z,  fmaf(e.w, d.w,  ad))));
        R  = fmaf(e.x, bo.x, fmaf(e.y, bo.y, fmaf(e.z, bo.z, fmaf(e.w, bo.w, R))));
    }
    float es = -(1.0f - 1.0f / ad) * qs[idx] / (R + EPS);

    g_S[idx] = make_float4(-X[idx * 3 + 0], -X[idx * 3 + 1], -X[idx * 3 + 2],
                           si + sj);

    // exact diagonal correction: the pair loop credits (si+sj)*r0_hw + wd
    // for the j==i pair; the true value is (si+sj+wd*D0)/(D0+eps).
    double part;
    {
        float d2c = 3e-6f;
        asm volatile("" : "+f"(d2c));        // block constant folding
        float r0_hw = rsqrtf(d2c);           // identical MUFU value as pair loop
        double D0 = (double)sqrtf(d2c);
        double w  = (double)si + (double)sj;
        double exact = (w + (double)wd * D0) / (D0 + (double)EPS);
        double loopv = w * (double)r0_hw + (double)wd;
        double corr = exact - loopv;          // pair-sum channel (coeff 0.5)
        part = (double)es + 0.5 * corr;
    }
#pragma unroll
    for (int off = 16; off > 0; off >>= 1)
        part += __shfl_down_sync(0xffffffffu, part, off);
    if ((tid & 31) == 0) red[tid >> 5] = part;
    __syncthreads();
    if (tid == 0) {
        double s = 0.0;
#pragma unroll
        for (int w = 0; w < PRE_THREADS / 32; w++) s += red[w];
        g_part_self[blockIdx.x] = s;
    }
}

// ============ kernel 2: symmetric pairwise + finalize ============
// Full matrix T = sum_ij w_i r_ij decomposed per 256-row panel p:
//   intra-panel [lo, lo+256):        sum w_i r_ij (full sub-matrix)
//   cross-panel [lo+256, 2048) once: sum (w_i + w_j) r_ij
// E_pair(batch) = T + wd*N^2 (+exact diag corr from k1)
__global__ void __launch_bounds__(PTHREADS, 12)
pair_kernel(const float* __restrict__ filt, float* __restrict__ out)
{
    __shared__ float redf[PTHREADS / 32];
    __shared__ bool isLast;

    const int tid = threadIdx.x;
    const int blk = blockIdx.x;
    const int b   = blk / BLKS_PER_B;
    const int r   = blk % BLKS_PER_B;

    // panel + split within panel; splits: 99,86,74,62,49,37,25,12 (sum 444)
    int p, rl, ns;
    if      (r <  99) { p = 0; rl = r;       ns = 99; }
    else if (r < 185) { p = 1; rl = r -  99; ns = 86; }
    else if (r < 259) { p = 2; rl = r - 185; ns = 74; }
    else if (r < 321) { p = 3; rl = r - 259; ns = 62; }
    else if (r < 370) { p = 4; rl = r - 321; ns = 49; }
    else if (r < 407) { p = 5; rl = r - 370; ns = 37; }
    else if (r < 432) { p = 6; rl = r - 407; ns = 25; }
    else              { p = 7; rl = r - 432; ns = 12; }

    const int lo  = PANEL * p;
    const int len = NN - lo;
    const int j0  = lo + (rl * len) / ns;
    const int j1  = lo + ((rl + 1) * len) / ns;
    const int selfEnd = lo + PANEL;
    const int jA1 = (j1 < selfEnd) ? j1 : selfEnd;
    const int jB0 = (j0 > selfEnd) ? j0 : selfEnd;

    const float4* __restrict__ S = g_S + b * NN;

    // this thread's PIB i-atoms within the panel
    float xi[PIB], yi[PIB], zi[PIB], wi[PIB], acc[PIB];
#pragma unroll
    for (int k = 0; k < PIB; k++) {
        float4 a = __ldg(&S[lo + k * PTHREADS + tid]);
        xi[k] = -a.x; yi[k] = -a.y; zi[k] = -a.z; wi[k] = a.w;
        acc[k] = 0.f;
    }
    float accw = 0.f;

    // ---- loop A: intra-panel region (full matrix, w_i weight) ----
#pragma unroll 4
    for (int j = j0; j < jA1; j++) {
        float4 pj = __ldg(&S[j]);          // negated coords, warp-uniform
#pragma unroll
        for (int k = 0; k < PIB; k++) {
            float dx = xi[k] + pj.x;
            float dy = yi[k] + pj.y;
            float dz = zi[k] + pj.z;
            float d2 = fmaf(dx, dx, fmaf(dy, dy, fmaf(dz, dz, 3e-6f)));
            acc[k] += rsqrtf(d2);
        }
    }

    // ---- loop B: cross-panel region (counted once, (w_i + w_j) weight) ----
#pragma unroll 4
    for (int j = jB0; j < j1; j++) {
        float4 pj = __ldg(&S[j]);
#pragma unroll
        for (int k = 0; k < PIB; k++) {
            float dx = xi[k] + pj.x;
            float dy = yi[k] + pj.y;
            float dz = zi[k] + pj.z;
            float d2 = fmaf(dx, dx, fmaf(dy, dy, fmaf(dz, dz, 3e-6f)));
            float rr = rsqrtf(d2);
            acc[k] += rr;
            accw = fmaf(pj.w, rr, accw);   // w_j side of symmetric pair
        }
    }

    // ---- fp32 combine + warp reduce (FP64 only once per block) ----
    float part = accw;
#pragma unroll
    for (int k = 0; k < PIB; k++)
        part = fmaf(wi[k], acc[k], part);
#pragma unroll
    for (int off = 16; off > 0; off >>= 1)
        part += __shfl_down_sync(0xffffffffu, part, off);
    if ((tid & 31) == 0) redf[tid >> 5] = part;
    __syncthreads();
    if (tid == 0) {
        double s = 0.0;
#pragma unroll
        for (int w = 0; w < PTHREADS / 32; w++) s += (double)redf[w];
        g_part_pair[blk] = s;
        __threadfence();
        unsigned int t = atomicAdd(&g_counter, 1u);
        isLast = (t == (unsigned)(gridDim.x - 1));
    }
    __syncthreads();
    if (!isLast) return;

    // ---- finalize: warp w (w<BB) handles batch w ----
    const int w = tid >> 5, lane = tid & 31;
    const float wd = filt[2 * CC];

    if (w < BB) {
        double pp = 0.0;
#pragma unroll
        for (int t = 0; t < 14; t++) {
            int idx = lane + t * 32;
            if (idx < BLKS_PER_B) pp += __ldcg(&g_part_pair[w * BLKS_PER_B + idx]);
        }
        double ss = (lane < PRE_BLOCKS / BB)
                  ? __ldcg(&g_part_self[w * (PRE_BLOCKS / BB) + lane]) : 0.0;
#pragma unroll
        for (int off = 16; off > 0; off >>= 1) {
            pp += __shfl_down_sync(0xffffffffu, pp, off);
            ss += __shfl_down_sync(0xffffffffu, ss, off);
        }
        if (lane == 0) {
            double pair = pp + (double)wd * (double)NN * (double)NN;
            float v = (float)((double)CONV * (ss + 0.5 * pair) * 0.01);
            if (isnan(v)) v = 1e-6f;
            out[w] = v;
        }
    }
    if (tid == 0) g_counter = 0;   // reset for next graph replay
}

extern "C" void kernel_launch(void* const* d_in, const int* in_sizes, int n_in,
                              void* d_out, int out_size) {
    const float* X    = (const float*)d_in[0];  // (B,N,3)
    const float* embs = (const float*)d_in[1];  // (B,N,C)
    const float* qs   = (const float*)d_in[2];  // (B,N)
    // d_in[3] = paired_mask (unused by reference)
    const float* born = (const float*)d_in[4];  // (C,)
    const float* die  = (const float*)d_in[5];  // (C,)
    const float* filt = (const float*)d_in[6];  // (2C+1, 1)
    float* out = (float*)d_out;

    precompute_kernel<<<PRE_BLOCKS, PRE_THREADS>>>(X, embs, qs, born, die, filt);
    pair_kernel<<<PBLOCKS, PTHREADS>>>(filt, out);
}

// round 16
// speedup vs baseline: 1.1136x; 1.0989x over previous
#include <cuda_runtime.h>
#include <math.h>

#define BB 4
#define NN 2048
#define CC 32
#define CONV 332.07156f
#define EPS 1e-6f

// ---- precompute geometry ----
#define PRE_THREADS 128
#define PRE_BLOCKS (BB * NN / PRE_THREADS)   // 64 (16 per batch)

// ---- pair geometry (symmetric 256-row panels, fine-grained) ----
#define PTHREADS 128
#define PIB 2                       // i-atoms per thread -> panel = 256
#define PANEL 256
#define BLKS_PER_B 370              // splits 82+72+62+51+41+31+21+10 (8 panels)
#define PBLOCKS (BB * BLKS_PER_B)   // 1480 = 10 CTAs/SM on 148 SMs
#define MAXJ 32                     // max j-range per block (actual <= 26)

// Scratch (no cudaMalloc allowed)
__device__ float4 g_S[BB * NN];            // {-x, -y, -z, w=s_i+s_j}
__device__ double g_part_pair[PBLOCKS];
__device__ double g_part_self[PRE_BLOCKS]; // self + 0.5*diag-correction
__device__ unsigned int g_counter = 0;

// ============ kernel 1: per-atom precompute + self/diag partials ============
__global__ void __launch_bounds__(PRE_THREADS)
precompute_kernel(const float* __restrict__ X,
                  const float* __restrict__ embs,
                  const float* __restrict__ qs,
                  const float* __restrict__ born,
                  const float* __restrict__ die,
                  const float* __restrict__ filt)
{
    __shared__ double red[PRE_THREADS / 32];
    const int tid = threadIdx.x;
    const int idx = blockIdx.x * PRE_THREADS + tid;
    const float wd = filt[2 * CC];

    const float4* e4 = (const float4*)(embs + (long)idx * CC);
    const float4* fi = (const float4*)(filt);
    const float4* fj = (const float4*)(filt + CC);
    const float4* d4 = (const float4*)(die);
    const float4* b4 = (const float4*)(born);

    float si = 0.f, sj = 0.f, ad = EPS, R = 1.0f;
#pragma unroll
    for (int c = 0; c < CC / 4; c++) {
        float4 e = e4[c];
        float4 a = fi[c], bq = fj[c], d = d4[c], bo = b4[c];
        si = fmaf(e.x, a.x,  fmaf(e.y, a.y,  fmaf(e.z, a.z,  fmaf(e.w, a.w,  si))));
        sj = fmaf(e.x, bq.x, fmaf(e.y, bq.y, fmaf(e.z, bq.z, fmaf(e.w, bq.w, sj))));
        ad = fmaf(e.x, d.x,  fmaf(e.y, d.y,  fmaf(e.z, d.z,  fmaf(e.w, d.w,  ad))));
        R  = fmaf(e.x, bo.x, fmaf(e.y, bo.y, fmaf(e.z, bo.z, fmaf(e.w, bo.w, R))));
    }
    float es = -(1.0f - 1.0f / ad) * qs[idx] / (R + EPS);

    g_S[idx] = make_float4(-X[idx * 3 + 0], -X[idx * 3 + 1], -X[idx * 3 + 2],
                           si + sj);

    // exact diagonal correction: the pair loop credits (si+sj)*r0_hw + wd
    // for the j==i pair; the true value is (si+sj+wd*D0)/(D0+eps).
    double part;
    {
        float d2c = 3e-6f;
        asm volatile("" : "+f"(d2c));        // block constant folding
        float r0_hw = rsqrtf(d2c);           // identical MUFU value as pair loop
        double D0 = (double)sqrtf(d2c);
        double w  = (double)si + (double)sj;
        double exact = (w + (double)wd * D0) / (D0 + (double)EPS);
        double loopv = w * (double)r0_hw + (double)wd;
        double corr = exact - loopv;          // pair-sum channel (coeff 0.5)
        part = (double)es + 0.5 * corr;
    }
#pragma unroll
    for (int off = 16; off > 0; off >>= 1)
        part += __shfl_down_sync(0xffffffffu, part, off);
    if ((tid & 31) == 0) red[tid >> 5] = part;
    __syncthreads();
    if (tid == 0) {
        double s = 0.0;
#pragma unroll
        for (int w = 0; w < PRE_THREADS / 32; w++) s += red[w];
        g_part_self[blockIdx.x] = s;
    }
}

// ============ kernel 2: symmetric pairwise + finalize ============
// Full matrix T = sum_ij w_i r_ij decomposed per 256-row panel p:
//   intra-panel [lo, lo+256):        sum w_i r_ij (full sub-matrix)
//   cross-panel [lo+256, 2048) once: sum (w_i + w_j) r_ij
// E_pair(batch) = T + wd*N^2 (+exact diag corr from k1)
__global__ void __launch_bounds__(PTHREADS, 10)
pair_kernel(const float* __restrict__ filt, float* __restrict__ out)
{
    __shared__ float4 sJ[MAXJ];         // this block's j-range, staged once
    __shared__ float redf[PTHREADS / 32];
    __shared__ bool isLast;

    const int tid = threadIdx.x;
    const int blk = blockIdx.x;
    const int b   = blk / BLKS_PER_B;
    const int r   = blk % BLKS_PER_B;

    // panel + split within panel; splits: 82,72,62,51,41,31,21,10 (sum 370)
    int p, rl, ns;
    if      (r <  82) { p = 0; rl = r;       ns = 82; }
    else if (r < 154) { p = 1; rl = r -  82; ns = 72; }
    else if (r < 216) { p = 2; rl = r - 154; ns = 62; }
    else if (r < 267) { p = 3; rl = r - 216; ns = 51; }
    else if (r < 308) { p = 4; rl = r - 267; ns = 41; }
    else if (r < 339) { p = 5; rl = r - 308; ns = 31; }
    else if (r < 360) { p = 6; rl = r - 339; ns = 21; }
    else              { p = 7; rl = r - 360; ns = 10; }

    const int lo  = PANEL * p;
    const int len = NN - lo;
    const int j0  = lo + (rl * len) / ns;
    const int j1  = lo + ((rl + 1) * len) / ns;
    const int selfEnd = lo + PANEL;
    const int jA1 = (j1 < selfEnd) ? j1 : selfEnd;
    const int jB0 = (j0 > selfEnd) ? j0 : selfEnd;
    const int cnt  = j1 - j0;           // <= 26
    const int aCnt = jA1 - j0;          // loop-A iterations (may be 0)
    const int bOff = jB0 - j0;          // loop-B start offset in sJ
    const int bEnd = cnt;               // loop-B end offset

    const float4* __restrict__ S = g_S + b * NN;

    // ---- stage j-range into shared (coalesced, one shot) ----
    if (tid < cnt) sJ[tid] = __ldg(&S[j0 + tid]);

    // this thread's PIB i-atoms within the panel
    float xi[PIB], yi[PIB], zi[PIB], wi[PIB], acc[PIB];
#pragma unroll
    for (int k = 0; k < PIB; k++) {
        float4 a = __ldg(&S[lo + k * PTHREADS + tid]);
        xi[k] = -a.x; yi[k] = -a.y; zi[k] = -a.z; wi[k] = a.w;
        acc[k] = 0.f;
    }
    float accw = 0.f;
    __syncthreads();

    // ---- loop A: intra-panel region (full matrix, w_i weight) ----
#pragma unroll 4
    for (int jj = 0; jj < aCnt; jj++) {
        float4 pj = sJ[jj];                // LDS.128 broadcast, 29 cyc
#pragma unroll
        for (int k = 0; k < PIB; k++) {
            float dx = xi[k] + pj.x;
            float dy = yi[k] + pj.y;
            float dz = zi[k] + pj.z;
            float d2 = fmaf(dx, dx, fmaf(dy, dy, fmaf(dz, dz, 3e-6f)));
            acc[k] += rsqrtf(d2);
        }
    }

    // ---- loop B: cross-panel region (counted once, (w_i + w_j) weight) ----
#pragma unroll 4
    for (int jj = bOff; jj < bEnd; jj++) {
        float4 pj = sJ[jj];
#pragma unroll
        for (int k = 0; k < PIB; k++) {
            float dx = xi[k] + pj.x;
            float dy = yi[k] + pj.y;
            float dz = zi[k] + pj.z;
            float d2 = fmaf(dx, dx, fmaf(dy, dy, fmaf(dz, dz, 3e-6f)));
            float rr = rsqrtf(d2);
            acc[k] += rr;
            accw = fmaf(pj.w, rr, accw);   // w_j side of symmetric pair
        }
    }

    // ---- fp32 combine + warp reduce (FP64 only once per block) ----
    float part = accw;
#pragma unroll
    for (int k = 0; k < PIB; k++)
        part = fmaf(wi[k], acc[k], part);
#pragma unroll
    for (int off = 16; off > 0; off >>= 1)
        part += __shfl_down_sync(0xffffffffu, part, off);
    if ((tid & 31) == 0) redf[tid >> 5] = part;
    __syncthreads();
    if (tid == 0) {
        double s = 0.0;
#pragma unroll
        for (int w = 0; w < PTHREADS / 32; w++) s += (double)redf[w];
        g_part_pair[blk] = s;
        __threadfence();
        unsigned int t = atomicAdd(&g_counter, 1u);
        isLast = (t == (unsigned)(gridDim.x - 1));
    }
    __syncthreads();
    if (!isLast) return;

    // ---- finalize: warp w (w<BB) handles batch w ----
    const int w = tid >> 5, lane = tid & 31;
    const float wd = filt[2 * CC];

    if (w < BB) {
        double pp = 0.0;
#pragma unroll
        for (int t = 0; t < 12; t++) {
            int idx = lane + t * 32;
            if (idx < BLKS_PER_B) pp += __ldcg(&g_part_pair[w * BLKS_PER_B + idx]);
        }
        double ss = (lane < PRE_BLOCKS / BB)
                  ? __ldcg(&g_part_self[w * (PRE_BLOCKS / BB) + lane]) : 0.0;
#pragma unroll
        for (int off = 16; off > 0; off >>= 1) {
            pp += __shfl_down_sync(0xffffffffu, pp, off);
            ss += __shfl_down_sync(0xffffffffu, ss, off);
        }
        if (lane == 0) {
            double pair = pp + (double)wd * (double)NN * (double)NN;
            float v = (float)((double)CONV * (ss + 0.5 * pair) * 0.01);
            if (isnan(v)) v = 1e-6f;
            out[w] = v;
        }
    }
    if (tid == 0) g_counter = 0;   // reset for next graph replay
}

extern "C" void kernel_launch(void* const* d_in, const int* in_sizes, int n_in,
                              void* d_out, int out_size) {
    const float* X    = (const float*)d_in[0];  // (B,N,3)
    const float* embs = (const float*)d_in[1];  // (B,N,C)
    const float* qs   = (const float*)d_in[2];  // (B,N)
    // d_in[3] = paired_mask (unused by reference)
    const float* born = (const float*)d_in[4];  // (C,)
    const float* die  = (const float*)d_in[5];  // (C,)
    const float* filt = (const float*)d_in[6];  // (2C+1, 1)
    float* out = (float*)d_out;

    precompute_kernel<<<PRE_BLOCKS, PRE_THREADS>>>(X, embs, qs, born, die, filt);
    pair_kernel<<<PBLOCKS, PTHREADS>>>(filt, out);
}

// round 17
// speedup vs baseline: 1.1364x; 1.0206x over previous
#include <cuda_runtime.h>
#include <math.h>

#define BB 4
#define NN 2048
#define CC 32
#define CONV 332.07156f
#define EPS 1e-6f

// ---- precompute geometry ----
#define PRE_THREADS 128
#define PRE_BLOCKS (BB * NN / PRE_THREADS)   // 64 (16 per batch)

// ---- pair geometry (symmetric 256-row panels, fine-grained) ----
#define PTHREADS 128
#define PIB 2                       // i-atoms per thread -> panel = 256
#define PANEL 256
#define BLKS_PER_B 370              // splits 82+72+62+51+41+31+21+10 (8 panels)
#define PBLOCKS (BB * BLKS_PER_B)   // 1480 = 10 CTAs/SM on 148 SMs
#define MAXJ 32                     // max j-range per block (actual <= 26)

typedef unsigned long long u64;

// Scratch (no cudaMalloc allowed)
__device__ float4 g_S[BB * NN];            // {-x, -y, -z, w=s_i+s_j}
__device__ double g_part_pair[PBLOCKS];
__device__ double g_part_self[PRE_BLOCKS]; // self + 0.5*diag-correction
__device__ unsigned int g_counter = 0;

// ---- packed f32x2 helpers (ptxas won't emit FFMA2 from C++) ----
__device__ __forceinline__ u64 pk2(float a, float b) {
    u64 r; asm("mov.b64 %0, {%1, %2};" : "=l"(r) : "f"(a), "f"(b)); return r;
}
__device__ __forceinline__ void upk2(float& a, float& b, u64 v) {
    asm("mov.b64 {%0, %1}, %2;" : "=f"(a), "=f"(b) : "l"(v));
}
__device__ __forceinline__ u64 add2(u64 a, u64 b) {
    u64 r; asm("add.rn.f32x2 %0, %1, %2;" : "=l"(r) : "l"(a), "l"(b)); return r;
}
__device__ __forceinline__ u64 fma2(u64 a, u64 b, u64 c) {
    u64 r; asm("fma.rn.f32x2 %0, %1, %2, %3;" : "=l"(r) : "l"(a), "l"(b), "l"(c)); return r;
}

// ============ kernel 1: per-atom precompute + self/diag partials ============
__global__ void __launch_bounds__(PRE_THREADS)
precompute_kernel(const float* __restrict__ X,
                  const float* __restrict__ embs,
                  const float* __restrict__ qs,
                  const float* __restrict__ born,
                  const float* __restrict__ die,
                  const float* __restrict__ filt)
{
    __shared__ double red[PRE_THREADS / 32];
    const int tid = threadIdx.x;
    const int idx = blockIdx.x * PRE_THREADS + tid;
    const float wd = filt[2 * CC];

    const float4* e4 = (const float4*)(embs + (long)idx * CC);
    const float4* fi = (const float4*)(filt);
    const float4* fj = (const float4*)(filt + CC);
    const float4* d4 = (const float4*)(die);
    const float4* b4 = (const float4*)(born);

    float si = 0.f, sj = 0.f, ad = EPS, R = 1.0f;
#pragma unroll
    for (int c = 0; c < CC / 4; c++) {
        float4 e = e4[c];
        float4 a = fi[c], bq = fj[c], d = d4[c], bo = b4[c];
        si = fmaf(e.x, a.x,  fmaf(e.y, a.y,  fmaf(e.z, a.z,  fmaf(e.w, a.w,  si))));
        sj = fmaf(e.x, bq.x, fmaf(e.y, bq.y, fmaf(e.z, bq.z, fmaf(e.w, bq.w, sj))));
        ad = fmaf(e.x, d.x,  fmaf(e.y, d.y,  fmaf(e.z, d.z,  fmaf(e.w, d.w,  ad))));
        R  = fmaf(e.x, bo.x, fmaf(e.y, bo.y, fmaf(e.z, bo.z, fmaf(e.w, bo.w, R))));
    }
    float es = -(1.0f - 1.0f / ad) * qs[idx] / (R + EPS);

    g_S[idx] = make_float4(-X[idx * 3 + 0], -X[idx * 3 + 1], -X[idx * 3 + 2],
                           si + sj);

    // exact diagonal correction: the pair loop credits (si+sj)*r0_hw + wd
    // for the j==i pair; the true value is (si+sj+wd*D0)/(D0+eps).
    double part;
    {
        float d2c = 3e-6f;
        asm volatile("" : "+f"(d2c));        // block constant folding
        float r0_hw = rsqrtf(d2c);           // identical MUFU value as pair loop
        double D0 = (double)sqrtf(d2c);
        double w  = (double)si + (double)sj;
        double exact = (w + (double)wd * D0) / (D0 + (double)EPS);
        double loopv = w * (double)r0_hw + (double)wd;
        double corr = exact - loopv;          // pair-sum channel (coeff 0.5)
        part = (double)es + 0.5 * corr;
    }
#pragma unroll
    for (int off = 16; off > 0; off >>= 1)
        part += __shfl_down_sync(0xffffffffu, part, off);
    if ((tid & 31) == 0) red[tid >> 5] = part;
    __syncthreads();
    if (tid == 0) {
        double s = 0.0;
#pragma unroll
        for (int w = 0; w < PRE_THREADS / 32; w++) s += red[w];
        g_part_self[blockIdx.x] = s;
    }
}

// ============ kernel 2: symmetric pairwise + finalize (packed f32x2) ============
// Full matrix T = sum_ij w_i r_ij decomposed per 256-row panel p:
//   intra-panel [lo, lo+256):        sum w_i r_ij (full sub-matrix)
//   cross-panel [lo+256, 2048) once: sum (w_i + w_j) r_ij
// E_pair(batch) = T + wd*N^2 (+exact diag corr from k1)
__global__ void __launch_bounds__(PTHREADS, 10)
pair_kernel(const float* __restrict__ filt, float* __restrict__ out)
{
    __shared__ ulonglong2 sJxy[MAXJ];   // {{-x,-x},{-y,-y}} pre-duplicated
    __shared__ ulonglong2 sJzw[MAXJ];   // {{-z,-z},{ w, w}}
    __shared__ float redf[PTHREADS / 32];
    __shared__ bool isLast;

    const int tid = threadIdx.x;
    const int blk = blockIdx.x;
    const int b   = blk / BLKS_PER_B;
    const int r   = blk % BLKS_PER_B;

    // panel + split within panel; splits: 82,72,62,51,41,31,21,10 (sum 370)
    int p, rl, ns;
    if      (r <  82) { p = 0; rl = r;       ns = 82; }
    else if (r < 154) { p = 1; rl = r -  82; ns = 72; }
    else if (r < 216) { p = 2; rl = r - 154; ns = 62; }
    else if (r < 267) { p = 3; rl = r - 216; ns = 51; }
    else if (r < 308) { p = 4; rl = r - 267; ns = 41; }
    else if (r < 339) { p = 5; rl = r - 308; ns = 31; }
    else if (r < 360) { p = 6; rl = r - 339; ns = 21; }
    else              { p = 7; rl = r - 360; ns = 10; }

    const int lo  = PANEL * p;
    const int len = NN - lo;
    const int j0  = lo + (rl * len) / ns;
    const int j1  = lo + ((rl + 1) * len) / ns;
    const int selfEnd = lo + PANEL;
    const int jA1 = (j1 < selfEnd) ? j1 : selfEnd;
    const int jB0 = (j0 > selfEnd) ? j0 : selfEnd;
    const int cnt  = j1 - j0;           // <= 26
    const int aCnt = jA1 - j0;          // loop-A iterations (may be 0)
    const int bOff = jB0 - j0;          // loop-B start offset in shared
    const int bEnd = cnt;

    const float4* __restrict__ S = g_S + b * NN;

    // ---- stage j-range into shared, pre-duplicated for packed math ----
    if (tid < cnt) {
        float4 s = __ldg(&S[j0 + tid]);          // negated coords + w
        sJxy[tid] = make_ulonglong2(pk2(s.x, s.x), pk2(s.y, s.y));
        sJzw[tid] = make_ulonglong2(pk2(s.z, s.z), pk2(s.w, s.w));
    }

    // this thread's 2 i-atoms packed into one f32x2 chain
    float4 a0 = __ldg(&S[lo + tid]);
    float4 a1 = __ldg(&S[lo + PTHREADS + tid]);
    const u64 xi2 = pk2(-a0.x, -a1.x);           // un-negate
    const u64 yi2 = pk2(-a0.y, -a1.y);
    const u64 zi2 = pk2(-a0.z, -a1.z);
    const float wi0 = a0.w, wi1 = a1.w;
    u64 acc2  = 0ull;                             // packed {sum_r(i0), sum_r(i1)}
    u64 accw2 = 0ull;                             // packed w_j*r accumul. (loop B)
    const u64 c3e6 = pk2(3e-6f, 3e-6f);
    __syncthreads();

    // ---- loop A: intra-panel region (full matrix, w_i weight) ----
#pragma unroll 4
    for (int jj = 0; jj < aCnt; jj++) {
        ulonglong2 jxy = sJxy[jj];               // LDS.128 -> 2 packed pairs
        ulonglong2 jzw = sJzw[jj];
        u64 dx2 = add2(xi2, jxy.x);
        u64 dy2 = add2(yi2, jxy.y);
        u64 dz2 = add2(zi2, jzw.x);
        u64 d2p = fma2(dz2, dz2, c3e6);
        d2p = fma2(dy2, dy2, d2p);
        d2p = fma2(dx2, dx2, d2p);
        float d2lo, d2hi;
        upk2(d2lo, d2hi, d2p);
        acc2 = add2(acc2, pk2(rsqrtf(d2lo), rsqrtf(d2hi)));
    }

    // ---- loop B: cross-panel region (counted once, (w_i + w_j) weight) ----
#pragma unroll 4
    for (int jj = bOff; jj < bEnd; jj++) {
        ulonglong2 jxy = sJxy[jj];
        ulonglong2 jzw = sJzw[jj];
        u64 dx2 = add2(xi2, jxy.x);
        u64 dy2 = add2(yi2, jxy.y);
        u64 dz2 = add2(zi2, jzw.x);
        u64 d2p = fma2(dz2, dz2, c3e6);
        d2p = fma2(dy2, dy2, d2p);
        d2p = fma2(dx2, dx2, d2p);
        float d2lo, d2hi;
        upk2(d2lo, d2hi, d2p);
        u64 r2 = pk2(rsqrtf(d2lo), rsqrtf(d2hi));
        acc2  = add2(acc2, r2);
        accw2 = fma2(jzw.y, r2, accw2);          // {w,w} * r, both lanes
    }

    // ---- fp32 combine + warp reduce (FP64 only once per block) ----
    float aclo, achi, awlo, awhi;
    upk2(aclo, achi, acc2);
    upk2(awlo, awhi, accw2);
    float part = fmaf(wi0, aclo, fmaf(wi1, achi, awlo + awhi));
#pragma unroll
    for (int off = 16; off > 0; off >>= 1)
        part += __shfl_down_sync(0xffffffffu, part, off);
    if ((tid & 31) == 0) redf[tid >> 5] = part;
    __syncthreads();
    if (tid == 0) {
        double s = 0.0;
#pragma unroll
        for (int w = 0; w < PTHREADS / 32; w++) s += (double)redf[w];
        g_part_pair[blk] = s;
        __threadfence();
        unsigned int t = atomicAdd(&g_counter, 1u);
        isLast = (t == (unsigned)(gridDim.x - 1));
    }
    __syncthreads();
    if (!isLast) return;

    // ---- finalize: warp w (w<BB) handles batch w ----
    const int w = tid >> 5, lane = tid & 31;
    const float wd = filt[2 * CC];

    if (w < BB) {
        double pp = 0.0;
#pragma unroll
        for (int t = 0; t < 12; t++) {
            int idx = lane + t * 32;
            if (idx < BLKS_PER_B) pp += __ldcg(&g_part_pair[w * BLKS_PER_B + idx]);
        }
        double ss = (lane < PRE_BLOCKS / BB)
                  ? __ldcg(&g_part_self[w * (PRE_BLOCKS / BB) + lane]) : 0.0;
#pragma unroll
        for (int off = 16; off > 0; off >>= 1) {
            pp += __shfl_down_sync(0xffffffffu, pp, off);
            ss += __shfl_down_sync(0xffffffffu, ss, off);
        }
        if (lane == 0) {
            double pair = pp + (double)wd * (double)NN * (double)NN;
            float v = (float)((double)CONV * (ss + 0.5 * pair) * 0.01);
            if (isnan(v)) v = 1e-6f;
            out[w] = v;
        }
    }
    if (tid == 0) g_counter = 0;   // reset for next graph replay
}

extern "C" void kernel_launch(void* const* d_in, const int* in_sizes, int n_in,
                              void* d_out, int out_size) {
    const float* X    = (const float*)d_in[0];  // (B,N,3)
    const float* embs = (const float*)d_in[1];  // (B,N,C)
    const float* qs   = (const float*)d_in[2];  // (B,N)
    // d_in[3] = paired_mask (unused by reference)
    const float* born = (const float*)d_in[4];  // (C,)
    const float* die  = (const float*)d_in[5];  // (C,)
    const float* filt = (const float*)d_in[6];  // (2C+1, 1)
    float* out = (float*)d_out;

    precompute_kernel<<<PRE_BLOCKS, PRE_THREADS>>>(X, embs, qs, born, die, filt);
    pair_kernel<<<PBLOCKS, PTHREADS>>>(filt, out);
}